// round 5
// baseline (speedup 1.0000x reference)
#include <cuda_runtime.h>
#include <cstdint>

// Problem constants
#define B_DIM 4096
#define E_DIM 1024
#define O_DIM 16
#define H_DIM 1024
#define KOH   (O_DIM * H_DIM)

// Tiling
#define TM 128
#define TN 128
#define BK 32
#define NCHUNK (E_DIM / BK)              // 32
#define NTHREADS 256
#define MAX_TILES (B_DIM / TM + O_DIM)   // 48

#define APITCH 136                       // floats; bank = idx + 8*row -> conflict-free
#define BUF_FLOATS (BK * APITCH)         // 4352 floats = 17408 B per buffer
#define SMEM_NEED (4 * BUF_FLOATS * 4)   // Abuf0, Abuf1, Bbuf0, Bbuf1 = 69632 B

// ---- device scratch (allocation-free) ----
__device__ int   g_perm[B_DIM];
__device__ int   g_tile_op[MAX_TILES];
__device__ int   g_tile_start[MAX_TILES];
__device__ int   g_tile_rows[MAX_TILES];
__device__ int   g_num_tiles;
__device__ float g_h1[(size_t)B_DIM * H_DIM];

// ============================================================================
// Helpers (baseline PTX only: mma.sync tf32 + cp.async, both sm_80+ features)
// ============================================================================
__device__ __forceinline__ uint32_t smem_u32(const void* p) {
    uint32_t a;
    asm("{ .reg .u64 t; cvta.to.shared.u64 t, %1; cvt.u32.u64 %0, t; }"
        : "=r"(a) : "l"(p));
    return a;
}
__device__ __forceinline__ void cp_async16(uint32_t dst, const void* src) {
    asm volatile("cp.async.ca.shared.global [%0], [%1], 16;" :: "r"(dst), "l"(src));
}
__device__ __forceinline__ void cp_commit() {
    asm volatile("cp.async.commit_group;" ::: "memory");
}
__device__ __forceinline__ void cp_wait_all() {
    asm volatile("cp.async.wait_group 0;" ::: "memory");
}
// fp32 -> tf32 hi/lo split (3xTF32 emulation)
__device__ __forceinline__ void split_tf32(float x, uint32_t& hi, uint32_t& lo) {
    asm("cvt.rna.tf32.f32 %0, %1;" : "=r"(hi) : "f"(x));
    float r = x - __uint_as_float(hi);
    asm("cvt.rna.tf32.f32 %0, %1;" : "=r"(lo) : "f"(r));
}
__device__ __forceinline__ void mma_m16n8k8(float* c, const uint32_t* a, const uint32_t* b) {
    asm volatile(
        "mma.sync.aligned.m16n8k8.row.col.f32.tf32.tf32.f32 "
        "{%0,%1,%2,%3}, {%4,%5,%6,%7}, {%8,%9}, {%0,%1,%2,%3};"
        : "+f"(c[0]), "+f"(c[1]), "+f"(c[2]), "+f"(c[3])
        : "r"(a[0]), "r"(a[1]), "r"(a[2]), "r"(a[3]), "r"(b[0]), "r"(b[1]));
}

// ============================================================================
// Setup: group examples by op; perm[] + per-128-row tile descriptors
// ============================================================================
__global__ void setup_kernel(const int* __restrict__ op_idx)
{
    __shared__ int cnt[O_DIM];
    __shared__ int cur[O_DIM];
    const int tid = threadIdx.x;
    const int nt  = blockDim.x;

    if (tid < O_DIM) cnt[tid] = 0;
    __syncthreads();
    for (int b = tid; b < B_DIM; b += nt)
        atomicAdd(&cnt[op_idx[b]], 1);
    __syncthreads();

    if (tid == 0) {
        int acc = 0, ntile = 0;
        for (int o = 0; o < O_DIM; o++) {
            cur[o] = acc;
            const int c = cnt[o];
            for (int t = 0; t < c; t += TM) {
                g_tile_op[ntile]    = o;
                g_tile_start[ntile] = acc + t;
                g_tile_rows[ntile]  = (c - t < TM) ? (c - t) : TM;
                ntile++;
            }
            acc += c;
        }
        g_num_tiles = ntile;
    }
    __syncthreads();

    for (int b = tid; b < B_DIM; b += nt) {
        const int o = op_idx[b];
        const int p = atomicAdd(&cur[o], 1);
        g_perm[p] = b;
    }
}

// ============================================================================
// Grouped GEMM, tensor cores via mma.sync tf32, 3-pass (hh + hl + lh).
//   LAYER 1: A rows gathered via perm from x;  Out = g_h1 (permuted order)
//   LAYER 2: A = g_h1 (contiguous);            Out scattered via perm
// smem layouts (pitch 136): As[k][m] (transposed on STS), Bs[k][n] (natural).
// ============================================================================
template <int LAYER>
__global__ __launch_bounds__(NTHREADS, 1)
void gemm_mma(const float* __restrict__ A, const float* __restrict__ W,
              const float* __restrict__ bias, float* __restrict__ Out)
{
    const int tile = blockIdx.x;
    if (tile >= g_num_tiles) return;

    const int op        = g_tile_op[tile];
    const int row_start = g_tile_start[tile];
    const int nrows     = g_tile_rows[tile];
    const int col_base  = blockIdx.y * TN;
    const int tid       = threadIdx.x;
    const int wid       = tid >> 5;
    const int lid       = tid & 31;
    const int warp_m    = wid >> 2;    // 0..1  (64 rows each)
    const int warp_n    = wid & 3;     // 0..3  (32 cols each)
    const int g         = lid >> 2;    // groupID 0..7
    const int tig       = lid & 3;     // thread-in-group 0..3

    extern __shared__ float smem[];
    float* Asb[2] = { smem,                  smem + BUF_FLOATS };
    float* Bsb[2] = { smem + 2 * BUF_FLOATS, smem + 3 * BUF_FLOATS };
    const uint32_t bs_addr[2] = { smem_u32(Bsb[0]), smem_u32(Bsb[1]) };

    // A loader: one row per thread (tid&127), half of the 32-k chunk (tid>>7)
    const int ar    = tid & 127;
    const int ahalf = (tid >> 7) * 16;
    const int arr   = (ar < nrows) ? ar : 0;
    const int asrc  = (LAYER == 1) ? g_perm[row_start + arr] : (row_start + arr);
    const float* aptr = A + (size_t)asrc * E_DIM + ahalf;

    // B loader: row kr = tid>>3; 4x 16B spanning 128 cols
    const int kr = tid >> 3;
    const float* wptr = W + (size_t)op * H_DIM + col_base
                          + (size_t)kr * KOH + (tid & 7) * 4;
    const uint32_t bdst = (uint32_t)(kr * APITCH + (tid & 7) * 4) * 4u;

    float acc[4][4][4];
    #pragma unroll
    for (int mt = 0; mt < 4; mt++)
        #pragma unroll
        for (int nt = 0; nt < 4; nt++)
            #pragma unroll
            for (int e = 0; e < 4; e++) acc[mt][nt][e] = 0.f;

    // ---- prologue: chunk 0 ----
    float4 ra[4];
    #pragma unroll
    for (int q = 0; q < 4; q++)
        ra[q] = *(const float4*)(aptr + q * 4);
    #pragma unroll
    for (int j = 0; j < 4; j++)
        cp_async16(bs_addr[0] + bdst + (uint32_t)(j * 32 * 4), wptr + j * 32);
    cp_commit();

    for (int kc = 0; kc < NCHUNK; kc++) {
        const int b = kc & 1;
        cp_wait_all();          // B(kc) resident
        __syncthreads();        // everyone done with buffers being overwritten

        // STS: transpose A regs -> As[k][m]
        #pragma unroll
        for (int q = 0; q < 4; q++) {
            float* d = Asb[b] + (ahalf + q * 4) * APITCH + ar;
            d[0 * APITCH] = ra[q].x;
            d[1 * APITCH] = ra[q].y;
            d[2 * APITCH] = ra[q].z;
            d[3 * APITCH] = ra[q].w;
        }
        __syncthreads();

        // prefetch chunk kc+1 (A -> regs, B -> other buffer via cp.async)
        if (kc + 1 < NCHUNK) {
            const int k0n = (kc + 1) * BK;
            #pragma unroll
            for (int q = 0; q < 4; q++)
                ra[q] = *(const float4*)(aptr + k0n + q * 4);
            #pragma unroll
            for (int j = 0; j < 4; j++)
                cp_async16(bs_addr[1 - b] + bdst + (uint32_t)(j * 32 * 4),
                           wptr + (size_t)k0n * KOH + j * 32);
            cp_commit();
        }

        // ---- compute chunk kc: 4 k-steps of 8 ----
        const float* Ab = Asb[b];
        const float* Bb = Bsb[b];
        #pragma unroll
        for (int ks = 0; ks < 4; ks++) {
            const int ko = ks * 8;

            uint32_t bh[4][2], bl[4][2];
            #pragma unroll
            for (int nt = 0; nt < 4; nt++) {
                const int c = warp_n * 32 + nt * 8 + g;
                split_tf32(Bb[(ko + tig)     * APITCH + c], bh[nt][0], bl[nt][0]);
                split_tf32(Bb[(ko + tig + 4) * APITCH + c], bh[nt][1], bl[nt][1]);
            }

            #pragma unroll
            for (int mt = 0; mt < 4; mt++) {
                const int rb = warp_m * 64 + mt * 16;
                uint32_t ah[4], al[4];
                split_tf32(Ab[(ko + tig)     * APITCH + rb + g    ], ah[0], al[0]);
                split_tf32(Ab[(ko + tig)     * APITCH + rb + g + 8], ah[1], al[1]);
                split_tf32(Ab[(ko + tig + 4) * APITCH + rb + g    ], ah[2], al[2]);
                split_tf32(Ab[(ko + tig + 4) * APITCH + rb + g + 8], ah[3], al[3]);
                #pragma unroll
                for (int nt = 0; nt < 4; nt++) {
                    mma_m16n8k8(acc[mt][nt], ah, bh[nt]);
                    mma_m16n8k8(acc[mt][nt], ah, bl[nt]);
                    mma_m16n8k8(acc[mt][nt], al, bh[nt]);
                }
            }
        }
    }

    // ---- epilogue: bias + relu, store (scatter via perm for layer 2) ----
    float2 bb[4];
    #pragma unroll
    for (int nt = 0; nt < 4; nt++) {
        const int c = col_base + warp_n * 32 + nt * 8 + 2 * tig;
        bb[nt] = *(const float2*)(bias + (size_t)op * H_DIM + c);
    }
    #pragma unroll
    for (int mt = 0; mt < 4; mt++) {
        #pragma unroll
        for (int h = 0; h < 2; h++) {
            const int r = warp_m * 64 + mt * 16 + h * 8 + g;
            if (r < nrows) {
                const int dst = (LAYER == 1) ? (row_start + r)
                                             : g_perm[row_start + r];
                float* orow = Out + (size_t)dst * H_DIM + col_base
                                  + warp_n * 32 + 2 * tig;
                #pragma unroll
                for (int nt = 0; nt < 4; nt++) {
                    float2 v;
                    v.x = fmaxf(acc[mt][nt][2 * h + 0] + bb[nt].x, 0.f);
                    v.y = fmaxf(acc[mt][nt][2 * h + 1] + bb[nt].y, 0.f);
                    *(float2*)(orow + nt * 8) = v;
                }
            }
        }
    }
}

// ============================================================================
// Launch
// ============================================================================
extern "C" void kernel_launch(void* const* d_in, const int* in_sizes, int n_in,
                              void* d_out, int out_size)
{
    const float* x      = (const float*)d_in[0];
    const int*   op_idx = (const int*)  d_in[1];
    const float* W1     = (const float*)d_in[2];
    const float* b1     = (const float*)d_in[3];
    const float* W2     = (const float*)d_in[4];
    const float* b2     = (const float*)d_in[5];
    float*       out    = (float*)d_out;
    (void)in_sizes; (void)n_in; (void)out_size;

    float* h1;
    cudaGetSymbolAddress((void**)&h1, g_h1);

    cudaFuncSetAttribute(gemm_mma<1>, cudaFuncAttributeMaxDynamicSharedMemorySize, SMEM_NEED);
    cudaFuncSetAttribute(gemm_mma<2>, cudaFuncAttributeMaxDynamicSharedMemorySize, SMEM_NEED);

    setup_kernel<<<1, 512>>>(op_idx);

    dim3 grid(MAX_TILES, H_DIM / TN);
    gemm_mma<1><<<grid, NTHREADS, SMEM_NEED>>>(x,  W1, b1, h1);
    gemm_mma<2><<<grid, NTHREADS, SMEM_NEED>>>(h1, W2, b2, out);
}

// round 6
// speedup vs baseline: 1.7373x; 1.7373x over previous
#include <cuda_runtime.h>
#include <cstdint>

// Problem constants
#define B_DIM 4096
#define E_DIM 1024
#define O_DIM 16
#define H_DIM 1024
#define KOH   (O_DIM * H_DIM)

// Tiling
#define TM 128
#define TN 128
#define BK 32
#define NCHUNK (E_DIM / BK)              // 32
#define NTHREADS 256
#define MAX_TILES (B_DIM / TM + O_DIM)   // 48

#define PITCH 136                        // floats; bank = idx + 8*k -> conflict-free
#define TILE_FLOATS (BK * PITCH)         // 4352
#define STAGE_FLOATS (4 * TILE_FLOATS)   // As_hi, As_lo, Bs_hi, Bs_lo
#define SMEM_NEED (2 * STAGE_FLOATS * 4) // 139264 B

// ---- device scratch (allocation-free) ----
__device__ int   g_perm[B_DIM];
__device__ int   g_tile_op[MAX_TILES];
__device__ int   g_tile_start[MAX_TILES];
__device__ int   g_tile_rows[MAX_TILES];
__device__ int   g_num_tiles;
__device__ float g_h1[(size_t)B_DIM * H_DIM];

// ============================================================================
// Helpers — baseline PTX only (mma.sync tf32 is sm_80+, valid on target sm_103)
// ============================================================================
__device__ __forceinline__ void split_tf32(float x, uint32_t& hi, uint32_t& lo) {
    asm("cvt.rna.tf32.f32 %0, %1;" : "=r"(hi) : "f"(x));
    float r = x - __uint_as_float(hi);
    asm("cvt.rna.tf32.f32 %0, %1;" : "=r"(lo) : "f"(r));
}

// Scalar l-value operands only: keeps accumulators SROA-able (register-resident).
#define MMA(c0, c1, c2, c3, a0, a1, a2, a3, b0, b1)                        \
    asm volatile(                                                          \
        "mma.sync.aligned.m16n8k8.row.col.f32.tf32.tf32.f32 "              \
        "{%0,%1,%2,%3}, {%4,%5,%6,%7}, {%8,%9}, {%0,%1,%2,%3};"            \
        : "+f"(c0), "+f"(c1), "+f"(c2), "+f"(c3)                           \
        : "r"(a0), "r"(a1), "r"(a2), "r"(a3), "r"(b0), "r"(b1))

// ============================================================================
// Setup: group examples by op; perm[] + per-128-row tile descriptors
// ============================================================================
__global__ void setup_kernel(const int* __restrict__ op_idx)
{
    __shared__ int cnt[O_DIM];
    __shared__ int cur[O_DIM];
    const int tid = threadIdx.x;
    const int nt  = blockDim.x;

    if (tid < O_DIM) cnt[tid] = 0;
    __syncthreads();
    for (int b = tid; b < B_DIM; b += nt)
        atomicAdd(&cnt[op_idx[b]], 1);
    __syncthreads();

    if (tid == 0) {
        int acc = 0, ntile = 0;
        for (int o = 0; o < O_DIM; o++) {
            cur[o] = acc;
            const int c = cnt[o];
            for (int t = 0; t < c; t += TM) {
                g_tile_op[ntile]    = o;
                g_tile_start[ntile] = acc + t;
                g_tile_rows[ntile]  = (c - t < TM) ? (c - t) : TM;
                ntile++;
            }
            acc += c;
        }
        g_num_tiles = ntile;
    }
    __syncthreads();

    for (int b = tid; b < B_DIM; b += nt) {
        const int o = op_idx[b];
        const int p = atomicAdd(&cur[o], 1);
        g_perm[p] = b;
    }
}

// ============================================================================
// Grouped GEMM, mma.sync tf32 3-pass (hh + hl + lh), hi/lo pre-split at STS.
//   LAYER 1: A rows gathered via perm from x;  Out = g_h1 (permuted order)
//   LAYER 2: A = g_h1 (contiguous);            Out scattered via perm
// smem: As_hi/As_lo[k][m], Bs_hi/Bs_lo[k][n], pitch 136, 2 stages, 1 sync/chunk
// ============================================================================
template <int LAYER>
__global__ __launch_bounds__(NTHREADS, 1)
void gemm_mma(const float* __restrict__ A, const float* __restrict__ W,
              const float* __restrict__ bias, float* __restrict__ Out)
{
    const int tile = blockIdx.x;
    if (tile >= g_num_tiles) return;

    const int op        = g_tile_op[tile];
    const int row_start = g_tile_start[tile];
    const int nrows     = g_tile_rows[tile];
    const int col_base  = blockIdx.y * TN;
    const int tid       = threadIdx.x;
    const int lid       = tid & 31;
    const int wid       = tid >> 5;
    const int warp_m    = wid >> 2;    // 0..1  (64 rows)
    const int warp_n    = wid & 3;     // 0..3  (32 cols)
    const int g         = lid >> 2;    // 0..7
    const int tig       = lid & 3;     // 0..3

    extern __shared__ uint32_t smem[];
    // stage s: As_hi +0, As_lo +T, Bs_hi +2T, Bs_lo +3T  (T = TILE_FLOATS)

    // A loader: row ar = tid&127, k-half ahalf = (tid>>7)*16
    const int ar    = tid & 127;
    const int ahalf = (tid >> 7) * 16;
    const int arr   = (ar < nrows) ? ar : 0;
    const int asrc  = (LAYER == 1) ? g_perm[row_start + arr] : (row_start + arr);
    const float* aptr = A + (size_t)asrc * E_DIM + ahalf;

    // B loader: k-row kr = tid>>3, col group (tid&7)*4, 4 float4 spanning 128 cols
    const int kr  = tid >> 3;
    const int bc4 = (tid & 7) * 4;
    const float* wptr = W + (size_t)op * H_DIM + col_base + (size_t)kr * KOH + bc4;

    float acc[4][4][4];
    #pragma unroll
    for (int mt = 0; mt < 4; mt++)
        #pragma unroll
        for (int nt = 0; nt < 4; nt++)
            #pragma unroll
            for (int e = 0; e < 4; e++) acc[mt][nt][e] = 0.f;

    // ---- prologue: fetch chunk 0 into registers ----
    float4 ra[4], rb[4];
    #pragma unroll
    for (int q = 0; q < 4; q++) ra[q] = *(const float4*)(aptr + q * 4);
    #pragma unroll
    for (int j = 0; j < 4; j++) rb[j] = *(const float4*)(wptr + j * 32);

    for (int kc = 0; kc < NCHUNK; kc++) {
        uint32_t* st = smem + (kc & 1) * STAGE_FLOATS;

        // ---- STS with hi/lo split ----
        #pragma unroll
        for (int q = 0; q < 4; q++) {          // A -> As_hi/As_lo[k][m]
            const float v[4] = { ra[q].x, ra[q].y, ra[q].z, ra[q].w };
            #pragma unroll
            for (int j = 0; j < 4; j++) {
                uint32_t hi, lo;
                split_tf32(v[j], hi, lo);
                const int k = ahalf + q * 4 + j;
                st[k * PITCH + ar]               = hi;
                st[TILE_FLOATS + k * PITCH + ar] = lo;
            }
        }
        #pragma unroll
        for (int j = 0; j < 4; j++) {          // B -> Bs_hi/Bs_lo[k][n], uint4 STS
            const float v[4] = { rb[j].x, rb[j].y, rb[j].z, rb[j].w };
            uint4 h4, l4;
            split_tf32(v[0], h4.x, l4.x);
            split_tf32(v[1], h4.y, l4.y);
            split_tf32(v[2], h4.z, l4.z);
            split_tf32(v[3], h4.w, l4.w);
            const int o = kr * PITCH + bc4 + j * 32;
            *(uint4*)&st[2 * TILE_FLOATS + o] = h4;
            *(uint4*)&st[3 * TILE_FLOATS + o] = l4;
        }
        __syncthreads();   // 2-stage: single sync per chunk is sufficient

        // ---- prefetch next chunk into registers ----
        if (kc + 1 < NCHUNK) {
            const int k0n = (kc + 1) * BK;
            #pragma unroll
            for (int q = 0; q < 4; q++) ra[q] = *(const float4*)(aptr + k0n + q * 4);
            #pragma unroll
            for (int j = 0; j < 4; j++) rb[j] = *(const float4*)(wptr + (size_t)k0n * KOH + j * 32);
        }

        // ---- compute: 4 k-steps of 8; pure LDS + MMA ----
        const uint32_t* Ah = st;
        const uint32_t* Al = st + TILE_FLOATS;
        const uint32_t* Bh = st + 2 * TILE_FLOATS;
        const uint32_t* Bl = st + 3 * TILE_FLOATS;
        #pragma unroll
        for (int ks = 0; ks < 4; ks++) {
            const int k0 = ks * 8 + tig;
            const int k1 = k0 + 4;

            uint32_t bh[4][2], bl[4][2];
            #pragma unroll
            for (int nt = 0; nt < 4; nt++) {
                const int c = warp_n * 32 + nt * 8 + g;
                bh[nt][0] = Bh[k0 * PITCH + c];
                bh[nt][1] = Bh[k1 * PITCH + c];
                bl[nt][0] = Bl[k0 * PITCH + c];
                bl[nt][1] = Bl[k1 * PITCH + c];
            }
            uint32_t ah[4][4], al[4][4];
            #pragma unroll
            for (int mt = 0; mt < 4; mt++) {
                const int rb0 = warp_m * 64 + mt * 16 + g;
                ah[mt][0] = Ah[k0 * PITCH + rb0];
                ah[mt][1] = Ah[k0 * PITCH + rb0 + 8];
                ah[mt][2] = Ah[k1 * PITCH + rb0];
                ah[mt][3] = Ah[k1 * PITCH + rb0 + 8];
                al[mt][0] = Al[k0 * PITCH + rb0];
                al[mt][1] = Al[k0 * PITCH + rb0 + 8];
                al[mt][2] = Al[k1 * PITCH + rb0];
                al[mt][3] = Al[k1 * PITCH + rb0 + 8];
            }
            // hh sweep, then hl, then lh: same-acc mma distance = 16
            #pragma unroll
            for (int mt = 0; mt < 4; mt++)
                #pragma unroll
                for (int nt = 0; nt < 4; nt++)
                    MMA(acc[mt][nt][0], acc[mt][nt][1], acc[mt][nt][2], acc[mt][nt][3],
                        ah[mt][0], ah[mt][1], ah[mt][2], ah[mt][3],
                        bh[nt][0], bh[nt][1]);
            #pragma unroll
            for (int mt = 0; mt < 4; mt++)
                #pragma unroll
                for (int nt = 0; nt < 4; nt++)
                    MMA(acc[mt][nt][0], acc[mt][nt][1], acc[mt][nt][2], acc[mt][nt][3],
                        ah[mt][0], ah[mt][1], ah[mt][2], ah[mt][3],
                        bl[nt][0], bl[nt][1]);
            #pragma unroll
            for (int mt = 0; mt < 4; mt++)
                #pragma unroll
                for (int nt = 0; nt < 4; nt++)
                    MMA(acc[mt][nt][0], acc[mt][nt][1], acc[mt][nt][2], acc[mt][nt][3],
                        al[mt][0], al[mt][1], al[mt][2], al[mt][3],
                        bh[nt][0], bh[nt][1]);
        }
        __syncthreads();   // protect stage (kc&1) before it is re-filled at kc+2
    }

    // ---- epilogue: bias + relu, store (scatter via perm for layer 2) ----
    float2 bb[4];
    #pragma unroll
    for (int nt = 0; nt < 4; nt++) {
        const int c = col_base + warp_n * 32 + nt * 8 + 2 * tig;
        bb[nt] = *(const float2*)(bias + (size_t)op * H_DIM + c);
    }
    #pragma unroll
    for (int mt = 0; mt < 4; mt++) {
        #pragma unroll
        for (int h = 0; h < 2; h++) {
            const int r = warp_m * 64 + mt * 16 + h * 8 + g;
            if (r < nrows) {
                const int dst = (LAYER == 1) ? (row_start + r)
                                             : g_perm[row_start + r];
                float* orow = Out + (size_t)dst * H_DIM + col_base
                                  + warp_n * 32 + 2 * tig;
                #pragma unroll
                for (int nt = 0; nt < 4; nt++) {
                    float2 v;
                    v.x = fmaxf(acc[mt][nt][2 * h + 0] + bb[nt].x, 0.f);
                    v.y = fmaxf(acc[mt][nt][2 * h + 1] + bb[nt].y, 0.f);
                    *(float2*)(orow + nt * 8) = v;
                }
            }
        }
    }
}

// ============================================================================
// Launch
// ============================================================================
extern "C" void kernel_launch(void* const* d_in, const int* in_sizes, int n_in,
                              void* d_out, int out_size)
{
    const float* x      = (const float*)d_in[0];
    const int*   op_idx = (const int*)  d_in[1];
    const float* W1     = (const float*)d_in[2];
    const float* b1     = (const float*)d_in[3];
    const float* W2     = (const float*)d_in[4];
    const float* b2     = (const float*)d_in[5];
    float*       out    = (float*)d_out;
    (void)in_sizes; (void)n_in; (void)out_size;

    float* h1;
    cudaGetSymbolAddress((void**)&h1, g_h1);

    cudaFuncSetAttribute(gemm_mma<1>, cudaFuncAttributeMaxDynamicSharedMemorySize, SMEM_NEED);
    cudaFuncSetAttribute(gemm_mma<2>, cudaFuncAttributeMaxDynamicSharedMemorySize, SMEM_NEED);

    setup_kernel<<<1, 512>>>(op_idx);

    dim3 grid(MAX_TILES, H_DIM / TN);
    gemm_mma<1><<<grid, NTHREADS, SMEM_NEED>>>(x,  W1, b1, h1);
    gemm_mma<2><<<grid, NTHREADS, SMEM_NEED>>>(h1, W2, b2, out);
}

// round 8
// speedup vs baseline: 2.3136x; 1.3317x over previous
#include <cuda_runtime.h>
#include <cuda_fp16.h>
#include <cstdint>

// Problem constants
#define B_DIM 4096
#define E_DIM 1024
#define O_DIM 16
#define H_DIM 1024
#define KOH   (O_DIM * H_DIM)

// Tiling
#define TM 128
#define TN 128
#define BK 32                            // k floats per chunk
#define KP 16                            // k-pairs per chunk
#define NCHUNK (E_DIM / BK)              // 32
#define NTHREADS 256
#define MAX_TILES (B_DIM / TM + O_DIM)   // 48

#define PITCH 136                        // u32 pitch; frag LDS bank = 8*tig+g -> conflict-free
#define TILE_U32 (KP * PITCH)            // 2176
#define STAGE_U32 (4 * TILE_U32)         // As_hi, As_lo, Bs_hi, Bs_lo
#define SMEM_NEED (2 * STAGE_U32 * 4)    // 69632 B

// ---- device scratch (allocation-free) ----
__device__ int   g_perm[B_DIM];
__device__ int   g_tile_op[MAX_TILES];
__device__ int   g_tile_start[MAX_TILES];
__device__ int   g_tile_rows[MAX_TILES];
__device__ int   g_num_tiles;
__device__ float g_h1[(size_t)B_DIM * H_DIM];

// ============================================================================
// Helpers — baseline PTX only (mma.sync m16n8k16 f16 is sm_80+)
// ============================================================================
// Split two floats into packed f16 hi-pair and lo-pair (3xFP16 emulation).
__device__ __forceinline__ void split2_f16(float v0, float v1,
                                           uint32_t& hi2, uint32_t& lo2) {
    __half2 h = __floats2half2_rn(v0, v1);          // low = v0
    float2  f = __half22float2(h);
    __half2 l = __floats2half2_rn(v0 - f.x, v1 - f.y);
    hi2 = *(uint32_t*)&h;
    lo2 = *(uint32_t*)&l;
}

// Scalar l-value operands only: keeps accumulators register-resident.
#define MMA(c0, c1, c2, c3, a0, a1, a2, a3, b0, b1)                        \
    asm volatile(                                                          \
        "mma.sync.aligned.m16n8k16.row.col.f32.f16.f16.f32 "               \
        "{%0,%1,%2,%3}, {%4,%5,%6,%7}, {%8,%9}, {%0,%1,%2,%3};"            \
        : "+f"(c0), "+f"(c1), "+f"(c2), "+f"(c3)                           \
        : "r"(a0), "r"(a1), "r"(a2), "r"(a3), "r"(b0), "r"(b1))

// ============================================================================
// Setup: group examples by op; perm[] + per-128-row tile descriptors
// ============================================================================
__global__ void setup_kernel(const int* __restrict__ op_idx)
{
    __shared__ int cnt[O_DIM];
    __shared__ int cur[O_DIM];
    const int tid = threadIdx.x;
    const int nt  = blockDim.x;

    if (tid < O_DIM) cnt[tid] = 0;
    __syncthreads();
    for (int b = tid; b < B_DIM; b += nt)
        atomicAdd(&cnt[op_idx[b]], 1);
    __syncthreads();

    if (tid == 0) {
        int acc = 0, ntile = 0;
        for (int o = 0; o < O_DIM; o++) {
            cur[o] = acc;
            const int c = cnt[o];
            for (int t = 0; t < c; t += TM) {
                g_tile_op[ntile]    = o;
                g_tile_start[ntile] = acc + t;
                g_tile_rows[ntile]  = (c - t < TM) ? (c - t) : TM;
                ntile++;
            }
            acc += c;
        }
        g_num_tiles = ntile;
    }
    __syncthreads();

    for (int b = tid; b < B_DIM; b += nt) {
        const int o = op_idx[b];
        const int p = atomicAdd(&cur[o], 1);
        g_perm[p] = b;
    }
}

// ============================================================================
// Grouped GEMM, mma.sync m16n8k16 fp16, 3-pass (hh + hl + lh).
// smem: packed k-pair u32 tiles As_hi/As_lo[kp][m], Bs_hi/Bs_lo[kp][n],
// pitch 136, 2 stages. Fragments are single scalar LDS of pre-packed pairs.
//   LAYER 1: A rows gathered via perm from x;  Out = g_h1 (permuted order)
//   LAYER 2: A = g_h1 (contiguous);            Out scattered via perm
// ============================================================================
template <int LAYER>
__global__ __launch_bounds__(NTHREADS, 1)
void gemm_mma(const float* __restrict__ A, const float* __restrict__ W,
              const float* __restrict__ bias, float* __restrict__ Out)
{
    const int tile = blockIdx.x;
    if (tile >= g_num_tiles) return;

    const int op        = g_tile_op[tile];
    const int row_start = g_tile_start[tile];
    const int nrows     = g_tile_rows[tile];
    const int col_base  = blockIdx.y * TN;
    const int tid       = threadIdx.x;
    const int lid       = tid & 31;
    const int wid       = tid >> 5;
    const int warp_m    = wid >> 2;    // 0..1  (64 rows)
    const int warp_n    = wid & 3;     // 0..3  (32 cols)
    const int g         = lid >> 2;    // 0..7
    const int tig       = lid & 3;     // 0..3

    extern __shared__ uint32_t smem[];
    // stage s: As_hi +0, As_lo +T, Bs_hi +2T, Bs_lo +3T  (T = TILE_U32)

    // A loader: row ar = tid&127, k-half (tid>>7)*16 floats -> 8 k-pairs
    const int ar   = tid & 127;
    const int akp0 = (tid >> 7) * 8;           // kp base
    const int arr  = (ar < nrows) ? ar : 0;
    const int asrc = (LAYER == 1) ? g_perm[row_start + arr] : (row_start + arr);
    const float* aptr = A + (size_t)asrc * E_DIM + akp0 * 2;

    // B loader: thread owns k-pair bkp = tid&15 (rows 2bkp, 2bkp+1) x 8 cols
    const int bkp = tid & 15;
    const int bn0 = (tid >> 4) * 8;
    const float* wptr = W + (size_t)op * H_DIM + col_base + bn0;

    float acc[4][4][4];
    #pragma unroll
    for (int mt = 0; mt < 4; mt++)
        #pragma unroll
        for (int nt = 0; nt < 4; nt++)
            #pragma unroll
            for (int e = 0; e < 4; e++) acc[mt][nt][e] = 0.f;

    // ---- prologue: fetch chunk 0 ----
    float4 ra[4];                 // A: 16 consecutive k
    float4 rb[4];                 // B: rows 2bkp,2bkp+1 x col-halves
    #pragma unroll
    for (int q = 0; q < 4; q++) ra[q] = *(const float4*)(aptr + q * 4);
    #pragma unroll
    for (int rr = 0; rr < 2; rr++)
        #pragma unroll
        for (int h = 0; h < 2; h++)
            rb[rr * 2 + h] = *(const float4*)(wptr + (size_t)(2 * bkp + rr) * KOH + h * 4);

    for (int kc = 0; kc < NCHUNK; kc++) {
        uint32_t* st = smem + (kc & 1) * STAGE_U32;

        // ---- STS with f16 hi/lo split, packed k-pairs ----
        #pragma unroll
        for (int q = 0; q < 4; q++) {          // A -> As[kp][m]
            const float v[4] = { ra[q].x, ra[q].y, ra[q].z, ra[q].w };
            #pragma unroll
            for (int p = 0; p < 2; p++) {
                uint32_t hi2, lo2;
                split2_f16(v[2 * p], v[2 * p + 1], hi2, lo2);
                const int kp = akp0 + q * 2 + p;
                st[kp * PITCH + ar]            = hi2;
                st[TILE_U32 + kp * PITCH + ar] = lo2;
            }
        }
        {                                       // B -> Bs[kp][n], uint4 STS
            uint4 h4[2], l4[2];
            #pragma unroll
            for (int h = 0; h < 2; h++) {
                const float* va = &rb[h].x;         // row 2bkp   (k even)
                const float* vb = &rb[2 + h].x;     // row 2bkp+1 (k odd)
                uint32_t* hp = &h4[h].x;
                uint32_t* lp = &l4[h].x;
                #pragma unroll
                for (int j = 0; j < 4; j++) {
                    __half2 hh = __floats2half2_rn(va[j], vb[j]);  // low = even k
                    float2  ff = __half22float2(hh);
                    __half2 ll = __floats2half2_rn(va[j] - ff.x, vb[j] - ff.y);
                    hp[j] = *(uint32_t*)&hh;
                    lp[j] = *(uint32_t*)&ll;
                }
                const int o = bkp * PITCH + bn0 + h * 4;
                *(uint4*)&st[2 * TILE_U32 + o] = h4[h];
                *(uint4*)&st[3 * TILE_U32 + o] = l4[h];
            }
        }
        __syncthreads();

        // ---- prefetch next chunk into registers ----
        if (kc + 1 < NCHUNK) {
            const int k0n = (kc + 1) * BK;
            #pragma unroll
            for (int q = 0; q < 4; q++)
                ra[q] = *(const float4*)(aptr + k0n + q * 4);
            #pragma unroll
            for (int rr = 0; rr < 2; rr++)
                #pragma unroll
                for (int h = 0; h < 2; h++)
                    rb[rr * 2 + h] = *(const float4*)(wptr + (size_t)(k0n + 2 * bkp + rr) * KOH + h * 4);
        }

        // ---- compute: 2 k-steps of 16; pure LDS + MMA ----
        const uint32_t* Ah = st;
        const uint32_t* Al = st + TILE_U32;
        const uint32_t* Bh = st + 2 * TILE_U32;
        const uint32_t* Bl = st + 3 * TILE_U32;
        #pragma unroll
        for (int ks = 0; ks < 2; ks++) {
            const int k0 = ks * 8 + tig;       // kp of a0/a1/b0
            const int k1 = k0 + 4;             // kp of a2/a3/b1

            uint32_t bh[4][2], bl[4][2];
            #pragma unroll
            for (int nt = 0; nt < 4; nt++) {
                const int c = warp_n * 32 + nt * 8 + g;
                bh[nt][0] = Bh[k0 * PITCH + c];
                bh[nt][1] = Bh[k1 * PITCH + c];
                bl[nt][0] = Bl[k0 * PITCH + c];
                bl[nt][1] = Bl[k1 * PITCH + c];
            }
            uint32_t ah[4][4], al[4][4];
            #pragma unroll
            for (int mt = 0; mt < 4; mt++) {
                const int m0 = warp_m * 64 + mt * 16 + g;
                ah[mt][0] = Ah[k0 * PITCH + m0];
                ah[mt][1] = Ah[k0 * PITCH + m0 + 8];
                ah[mt][2] = Ah[k1 * PITCH + m0];
                ah[mt][3] = Ah[k1 * PITCH + m0 + 8];
                al[mt][0] = Al[k0 * PITCH + m0];
                al[mt][1] = Al[k0 * PITCH + m0 + 8];
                al[mt][2] = Al[k1 * PITCH + m0];
                al[mt][3] = Al[k1 * PITCH + m0 + 8];
            }
            // hh, hl, lh sweeps: same-acc mma distance = 16
            #pragma unroll
            for (int mt = 0; mt < 4; mt++)
                #pragma unroll
                for (int nt = 0; nt < 4; nt++)
                    MMA(acc[mt][nt][0], acc[mt][nt][1], acc[mt][nt][2], acc[mt][nt][3],
                        ah[mt][0], ah[mt][1], ah[mt][2], ah[mt][3],
                        bh[nt][0], bh[nt][1]);
            #pragma unroll
            for (int mt = 0; mt < 4; mt++)
                #pragma unroll
                for (int nt = 0; nt < 4; nt++)
                    MMA(acc[mt][nt][0], acc[mt][nt][1], acc[mt][nt][2], acc[mt][nt][3],
                        ah[mt][0], ah[mt][1], ah[mt][2], ah[mt][3],
                        bl[nt][0], bl[nt][1]);
            #pragma unroll
            for (int mt = 0; mt < 4; mt++)
                #pragma unroll
                for (int nt = 0; nt < 4; nt++)
                    MMA(acc[mt][nt][0], acc[mt][nt][1], acc[mt][nt][2], acc[mt][nt][3],
                        al[mt][0], al[mt][1], al[mt][2], al[mt][3],
                        bh[nt][0], bh[nt][1]);
        }
        __syncthreads();
    }

    // ---- epilogue: bias + relu, store (scatter via perm for layer 2) ----
    float2 bb[4];
    #pragma unroll
    for (int nt = 0; nt < 4; nt++) {
        const int c = col_base + warp_n * 32 + nt * 8 + 2 * tig;
        bb[nt] = *(const float2*)(bias + (size_t)op * H_DIM + c);
    }
    #pragma unroll
    for (int mt = 0; mt < 4; mt++) {
        #pragma unroll
        for (int h = 0; h < 2; h++) {
            const int r = warp_m * 64 + mt * 16 + h * 8 + g;
            if (r < nrows) {
                const int dst = (LAYER == 1) ? (row_start + r)
                                             : g_perm[row_start + r];
                float* orow = Out + (size_t)dst * H_DIM + col_base
                                  + warp_n * 32 + 2 * tig;
                #pragma unroll
                for (int nt = 0; nt < 4; nt++) {
                    float2 v;
                    v.x = fmaxf(acc[mt][nt][2 * h + 0] + bb[nt].x, 0.f);
                    v.y = fmaxf(acc[mt][nt][2 * h + 1] + bb[nt].y, 0.f);
                    *(float2*)(orow + nt * 8) = v;
                }
            }
        }
    }
}

// ============================================================================
// Launch
// ============================================================================
extern "C" void kernel_launch(void* const* d_in, const int* in_sizes, int n_in,
                              void* d_out, int out_size)
{
    const float* x      = (const float*)d_in[0];
    const int*   op_idx = (const int*)  d_in[1];
    const float* W1     = (const float*)d_in[2];
    const float* b1     = (const float*)d_in[3];
    const float* W2     = (const float*)d_in[4];
    const float* b2     = (const float*)d_in[5];
    float*       out    = (float*)d_out;
    (void)in_sizes; (void)n_in; (void)out_size;

    float* h1;
    cudaGetSymbolAddress((void**)&h1, g_h1);

    cudaFuncSetAttribute(gemm_mma<1>, cudaFuncAttributeMaxDynamicSharedMemorySize, SMEM_NEED);
    cudaFuncSetAttribute(gemm_mma<2>, cudaFuncAttributeMaxDynamicSharedMemorySize, SMEM_NEED);

    setup_kernel<<<1, 512>>>(op_idx);

    dim3 grid(MAX_TILES, H_DIM / TN);
    gemm_mma<1><<<grid, NTHREADS, SMEM_NEED>>>(x,  W1, b1, h1);
    gemm_mma<2><<<grid, NTHREADS, SMEM_NEED>>>(h1, W2, b2, out);
}

// round 10
// speedup vs baseline: 2.3572x; 1.0189x over previous
#include <cuda_runtime.h>
#include <cuda_fp16.h>
#include <cstdint>

// Problem constants
#define B_DIM 4096
#define E_DIM 1024
#define O_DIM 16
#define H_DIM 1024
#define KOH   (O_DIM * H_DIM)

// Tiling
#define TM 128
#define TN 128
#define BK 32                            // k floats per chunk
#define KP 16                            // k-pairs per chunk
#define NCHUNK (E_DIM / BK)              // 32
#define NTHREADS 256
#define MAX_TILES (B_DIM / TM + O_DIM)   // 48

#define PITCH 136                        // u32 pitch; frag LDS bank = 8*tig+g -> conflict-free
#define TILE_U32 (KP * PITCH)            // 2176
#define STAGE_U32 (4 * TILE_U32)         // As_hi, As_lo, Bs_hi, Bs_lo
#define SMEM_NEED (2 * STAGE_U32 * 4)    // 69632 B  (x2 CTAs = 139KB < 228KB)

// ---- device scratch (allocation-free) ----
__device__ int   g_perm[B_DIM];
__device__ int   g_tile_op[MAX_TILES];
__device__ int   g_tile_start[MAX_TILES];
__device__ int   g_tile_rows[MAX_TILES];
__device__ int   g_num_tiles;
__device__ float g_h1[(size_t)B_DIM * H_DIM];

// ============================================================================
// Helpers — baseline PTX only (mma.sync m16n8k16 f16 is sm_80+)
// ============================================================================
__device__ __forceinline__ void split2_f16(float v0, float v1,
                                           uint32_t& hi2, uint32_t& lo2) {
    __half2 h = __floats2half2_rn(v0, v1);          // low = v0
    float2  f = __half22float2(h);
    __half2 l = __floats2half2_rn(v0 - f.x, v1 - f.y);
    hi2 = *(uint32_t*)&h;
    lo2 = *(uint32_t*)&l;
}

// Scalar l-value operands only: keeps accumulators register-resident.
#define MMA(c0, c1, c2, c3, a0, a1, a2, a3, b0, b1)                        \
    asm volatile(                                                          \
        "mma.sync.aligned.m16n8k16.row.col.f32.f16.f16.f32 "               \
        "{%0,%1,%2,%3}, {%4,%5,%6,%7}, {%8,%9}, {%0,%1,%2,%3};"            \
        : "+f"(c0), "+f"(c1), "+f"(c2), "+f"(c3)                           \
        : "r"(a0), "r"(a1), "r"(a2), "r"(a3), "r"(b0), "r"(b1))

// ============================================================================
// Setup: group examples by op; perm[] + per-128-row tile descriptors
// ============================================================================
__global__ void setup_kernel(const int* __restrict__ op_idx)
{
    __shared__ int cnt[O_DIM];
    __shared__ int cur[O_DIM];
    const int tid = threadIdx.x;
    const int nt  = blockDim.x;

    if (tid < O_DIM) cnt[tid] = 0;
    __syncthreads();
    for (int b = tid; b < B_DIM; b += nt)
        atomicAdd(&cnt[op_idx[b]], 1);
    __syncthreads();

    if (tid == 0) {
        int acc = 0, ntile = 0;
        for (int o = 0; o < O_DIM; o++) {
            cur[o] = acc;
            const int c = cnt[o];
            for (int t = 0; t < c; t += TM) {
                g_tile_op[ntile]    = o;
                g_tile_start[ntile] = acc + t;
                g_tile_rows[ntile]  = (c - t < TM) ? (c - t) : TM;
                ntile++;
            }
            acc += c;
        }
        g_num_tiles = ntile;
    }
    __syncthreads();

    for (int b = tid; b < B_DIM; b += nt) {
        const int o = op_idx[b];
        const int p = atomicAdd(&cur[o], 1);
        g_perm[p] = b;
    }
}

// ============================================================================
// Grouped GEMM, mma.sync m16n8k16 fp16, 3-pass (hh + hl + lh).
// Single __syncthreads per chunk: iteration kc writes stage (kc+1)&1 then
// computes stage kc&1; the top-of-loop barrier orders both hazards.
// __launch_bounds__(256,2): 2 CTAs/SM so a co-resident CTA's HMMAs cover
// this CTA's LDS latency and barrier drains.
//   LAYER 1: A rows gathered via perm from x;  Out = g_h1 (permuted order)
//   LAYER 2: A = g_h1 (contiguous);            Out scattered via perm
// ============================================================================
template <int LAYER>
__global__ __launch_bounds__(NTHREADS, 2)
void gemm_mma(const float* __restrict__ A, const float* __restrict__ W,
              const float* __restrict__ bias, float* __restrict__ Out)
{
    const int tile = blockIdx.x;
    if (tile >= g_num_tiles) return;

    const int op        = g_tile_op[tile];
    const int row_start = g_tile_start[tile];
    const int nrows     = g_tile_rows[tile];
    const int col_base  = blockIdx.y * TN;
    const int tid       = threadIdx.x;
    const int lid       = tid & 31;
    const int wid       = tid >> 5;
    const int warp_m    = wid >> 2;    // 0..1  (64 rows)
    const int warp_n    = wid & 3;     // 0..3  (32 cols)
    const int g         = lid >> 2;    // 0..7
    const int tig       = lid & 3;     // 0..3

    extern __shared__ uint32_t smem[];
    // stage s: As_hi +0, As_lo +T, Bs_hi +2T, Bs_lo +3T  (T = TILE_U32)

    // A loader: row ar = tid&127, k-half (tid>>7)*16 floats -> 8 k-pairs
    const int ar   = tid & 127;
    const int akp0 = (tid >> 7) * 8;
    const int arr  = (ar < nrows) ? ar : 0;
    const int asrc = (LAYER == 1) ? g_perm[row_start + arr] : (row_start + arr);
    const float* aptr = A + (size_t)asrc * E_DIM + akp0 * 2;

    // B loader: thread owns k-pair bkp = tid&15 (rows 2bkp, 2bkp+1) x 8 cols
    const int bkp = tid & 15;
    const int bn0 = (tid >> 4) * 8;
    const float* wptr = W + (size_t)op * H_DIM + col_base + bn0;

    float acc[4][4][4];
    #pragma unroll
    for (int mt = 0; mt < 4; mt++)
        #pragma unroll
        for (int nt = 0; nt < 4; nt++)
            #pragma unroll
            for (int e = 0; e < 4; e++) acc[mt][nt][e] = 0.f;

    float4 ra[4];                 // A: 16 consecutive k of next-to-store chunk
    float4 rb[4];                 // B: rows 2bkp,2bkp+1 x col-halves

    // STS of regs -> stage st (split to f16 hi/lo, packed k-pairs)
    auto do_sts = [&](uint32_t* st) {
        #pragma unroll
        for (int q = 0; q < 4; q++) {          // A -> As[kp][m]
            const float v[4] = { ra[q].x, ra[q].y, ra[q].z, ra[q].w };
            #pragma unroll
            for (int p = 0; p < 2; p++) {
                uint32_t hi2, lo2;
                split2_f16(v[2 * p], v[2 * p + 1], hi2, lo2);
                const int kp = akp0 + q * 2 + p;
                st[kp * PITCH + ar]            = hi2;
                st[TILE_U32 + kp * PITCH + ar] = lo2;
            }
        }
        #pragma unroll
        for (int h = 0; h < 2; h++) {          // B -> Bs[kp][n], uint4 STS
            const float* va = &rb[h].x;         // row 2bkp   (k even)
            const float* vb = &rb[2 + h].x;     // row 2bkp+1 (k odd)
            uint4 h4, l4;
            uint32_t* hp = &h4.x;
            uint32_t* lp = &l4.x;
            #pragma unroll
            for (int j = 0; j < 4; j++) {
                __half2 hh = __floats2half2_rn(va[j], vb[j]);  // low = even k
                float2  ff = __half22float2(hh);
                __half2 ll = __floats2half2_rn(va[j] - ff.x, vb[j] - ff.y);
                hp[j] = *(uint32_t*)&hh;
                lp[j] = *(uint32_t*)&ll;
            }
            const int o = bkp * PITCH + bn0 + h * 4;
            *(uint4*)&st[2 * TILE_U32 + o] = h4;
            *(uint4*)&st[3 * TILE_U32 + o] = l4;
        }
    };
    auto do_ldg = [&](int kc) {
        const int k0 = kc * BK;
        #pragma unroll
        for (int q = 0; q < 4; q++)
            ra[q] = *(const float4*)(aptr + k0 + q * 4);
        #pragma unroll
        for (int rr = 0; rr < 2; rr++)
            #pragma unroll
            for (int h = 0; h < 2; h++)
                rb[rr * 2 + h] = *(const float4*)(wptr + (size_t)(k0 + 2 * bkp + rr) * KOH + h * 4);
    };

    // ---- prologue: chunk 0 -> stage 0; chunk 1 -> regs ----
    do_ldg(0);
    do_sts(smem);
    do_ldg(1);

    for (int kc = 0; kc < NCHUNK; kc++) {
        __syncthreads();   // stage kc&1 STS visible; compute of kc-1 finished

        if (kc + 1 < NCHUNK)
            do_sts(smem + ((kc + 1) & 1) * STAGE_U32);
        if (kc + 2 < NCHUNK)
            do_ldg(kc + 2);

        // ---- compute chunk kc: 2 k-steps of 16; per-mt fragment loads ----
        const uint32_t* st = smem + (kc & 1) * STAGE_U32;
        const uint32_t* Ah = st;
        const uint32_t* Al = st + TILE_U32;
        const uint32_t* Bh = st + 2 * TILE_U32;
        const uint32_t* Bl = st + 3 * TILE_U32;
        #pragma unroll
        for (int ks = 0; ks < 2; ks++) {
            const int k0 = ks * 8 + tig;
            const int k1 = k0 + 4;

            uint32_t bh[4][2], bl[4][2];
            #pragma unroll
            for (int nt = 0; nt < 4; nt++) {
                const int c = warp_n * 32 + nt * 8 + g;
                bh[nt][0] = Bh[k0 * PITCH + c];
                bh[nt][1] = Bh[k1 * PITCH + c];
                bl[nt][0] = Bl[k0 * PITCH + c];
                bl[nt][1] = Bl[k1 * PITCH + c];
            }
            #pragma unroll
            for (int mt = 0; mt < 4; mt++) {
                const int m0 = warp_m * 64 + mt * 16 + g;
                uint32_t ah0 = Ah[k0 * PITCH + m0];
                uint32_t ah1 = Ah[k0 * PITCH + m0 + 8];
                uint32_t ah2 = Ah[k1 * PITCH + m0];
                uint32_t ah3 = Ah[k1 * PITCH + m0 + 8];
                uint32_t al0 = Al[k0 * PITCH + m0];
                uint32_t al1 = Al[k0 * PITCH + m0 + 8];
                uint32_t al2 = Al[k1 * PITCH + m0];
                uint32_t al3 = Al[k1 * PITCH + m0 + 8];
                // hh sweep (same-acc distance 4), then hl, then lh
                #pragma unroll
                for (int nt = 0; nt < 4; nt++)
                    MMA(acc[mt][nt][0], acc[mt][nt][1], acc[mt][nt][2], acc[mt][nt][3],
                        ah0, ah1, ah2, ah3, bh[nt][0], bh[nt][1]);
                #pragma unroll
                for (int nt = 0; nt < 4; nt++)
                    MMA(acc[mt][nt][0], acc[mt][nt][1], acc[mt][nt][2], acc[mt][nt][3],
                        ah0, ah1, ah2, ah3, bl[nt][0], bl[nt][1]);
                #pragma unroll
                for (int nt = 0; nt < 4; nt++)
                    MMA(acc[mt][nt][0], acc[mt][nt][1], acc[mt][nt][2], acc[mt][nt][3],
                        al0, al1, al2, al3, bh[nt][0], bh[nt][1]);
            }
        }
    }

    // ---- epilogue: bias + relu, store (scatter via perm for layer 2) ----
    float2 bb[4];
    #pragma unroll
    for (int nt = 0; nt < 4; nt++) {
        const int c = col_base + warp_n * 32 + nt * 8 + 2 * tig;
        bb[nt] = *(const float2*)(bias + (size_t)op * H_DIM + c);
    }
    #pragma unroll
    for (int mt = 0; mt < 4; mt++) {
        #pragma unroll
        for (int h = 0; h < 2; h++) {
            const int r = warp_m * 64 + mt * 16 + h * 8 + g;
            if (r < nrows) {
                const int dst = (LAYER == 1) ? (row_start + r)
                                             : g_perm[row_start + r];
                float* orow = Out + (size_t)dst * H_DIM + col_base
                                  + warp_n * 32 + 2 * tig;
                #pragma unroll
                for (int nt = 0; nt < 4; nt++) {
                    float2 v;
                    v.x = fmaxf(acc[mt][nt][2 * h + 0] + bb[nt].x, 0.f);
                    v.y = fmaxf(acc[mt][nt][2 * h + 1] + bb[nt].y, 0.f);
                    *(float2*)(orow + nt * 8) = v;
                }
            }
        }
    }
}

// ============================================================================
// Launch
// ============================================================================
extern "C" void kernel_launch(void* const* d_in, const int* in_sizes, int n_in,
                              void* d_out, int out_size)
{
    const float* x      = (const float*)d_in[0];
    const int*   op_idx = (const int*)  d_in[1];
    const float* W1     = (const float*)d_in[2];
    const float* b1     = (const float*)d_in[3];
    const float* W2     = (const float*)d_in[4];
    const float* b2     = (const float*)d_in[5];
    float*       out    = (float*)d_out;
    (void)in_sizes; (void)n_in; (void)out_size;

    float* h1;
    cudaGetSymbolAddress((void**)&h1, g_h1);

    cudaFuncSetAttribute(gemm_mma<1>, cudaFuncAttributeMaxDynamicSharedMemorySize, SMEM_NEED);
    cudaFuncSetAttribute(gemm_mma<2>, cudaFuncAttributeMaxDynamicSharedMemorySize, SMEM_NEED);

    setup_kernel<<<1, 512>>>(op_idx);

    dim3 grid(MAX_TILES, H_DIM / TN);
    gemm_mma<1><<<grid, NTHREADS, SMEM_NEED>>>(x,  W1, b1, h1);
    gemm_mma<2><<<grid, NTHREADS, SMEM_NEED>>>(h1, W2, b2, out);
}